// round 1
// baseline (speedup 1.0000x reference)
#include <cuda_runtime.h>

// D = 16777216 floats per vector; n4 = D/4 float4 elements.
// Output: out[0..D) = x, out[D..D+6) = {ly0·x, ly1·x, ly1·ly0, ly2·x, ly2·ly0, ly2·ly1}

__global__ void zero_tail_kernel(float* __restrict__ out, int D) {
    if (threadIdx.x < 6) out[D + threadIdx.x] = 0.0f;
}

__global__ void __launch_bounds__(256)
dlrm_fused_kernel(const float4* __restrict__ xv,
                  const float4* __restrict__ l0v,
                  const float4* __restrict__ l1v,
                  const float4* __restrict__ l2v,
                  float4* __restrict__ outx,
                  float* __restrict__ out_tail,
                  int n4) {
    float s0 = 0.f, s1 = 0.f, s2 = 0.f, s3 = 0.f, s4 = 0.f, s5 = 0.f;

    const int stride = gridDim.x * blockDim.x;
    for (int i = blockIdx.x * blockDim.x + threadIdx.x; i < n4; i += stride) {
        const float4 a = xv[i];
        const float4 b = l0v[i];
        const float4 c = l1v[i];
        const float4 d = l2v[i];
        outx[i] = a;  // fused copy of x into out

        s0 += b.x * a.x + b.y * a.y + b.z * a.z + b.w * a.w;  // ly0 · x
        s1 += c.x * a.x + c.y * a.y + c.z * a.z + c.w * a.w;  // ly1 · x
        s2 += c.x * b.x + c.y * b.y + c.z * b.z + c.w * b.w;  // ly1 · ly0
        s3 += d.x * a.x + d.y * a.y + d.z * a.z + d.w * a.w;  // ly2 · x
        s4 += d.x * b.x + d.y * b.y + d.z * b.z + d.w * b.w;  // ly2 · ly0
        s5 += d.x * c.x + d.y * c.y + d.z * c.z + d.w * c.w;  // ly2 · ly1
    }

    // Warp-level reduction
    #pragma unroll
    for (int off = 16; off > 0; off >>= 1) {
        s0 += __shfl_down_sync(0xFFFFFFFFu, s0, off);
        s1 += __shfl_down_sync(0xFFFFFFFFu, s1, off);
        s2 += __shfl_down_sync(0xFFFFFFFFu, s2, off);
        s3 += __shfl_down_sync(0xFFFFFFFFu, s3, off);
        s4 += __shfl_down_sync(0xFFFFFFFFu, s4, off);
        s5 += __shfl_down_sync(0xFFFFFFFFu, s5, off);
    }

    __shared__ float smem[6][8];  // 256 threads = 8 warps
    const int warp = threadIdx.x >> 5;
    const int lane = threadIdx.x & 31;
    if (lane == 0) {
        smem[0][warp] = s0; smem[1][warp] = s1; smem[2][warp] = s2;
        smem[3][warp] = s3; smem[4][warp] = s4; smem[5][warp] = s5;
    }
    __syncthreads();

    // First 6 threads each reduce one product across the 8 warps and atomically add.
    if (threadIdx.x < 6) {
        float v = 0.f;
        #pragma unroll
        for (int w = 0; w < 8; w++) v += smem[threadIdx.x][w];
        atomicAdd(out_tail + threadIdx.x, v);
    }
}

extern "C" void kernel_launch(void* const* d_in, const int* in_sizes, int n_in,
                              void* d_out, int out_size) {
    const float* x  = (const float*)d_in[0];
    const float* l0 = (const float*)d_in[1];
    const float* l1 = (const float*)d_in[2];
    const float* l2 = (const float*)d_in[3];
    float* out = (float*)d_out;

    const int D  = in_sizes[0];   // 16777216
    const int n4 = D / 4;         // 4194304

    zero_tail_kernel<<<1, 32>>>(out, D);

    const int threads = 256;
    int blocks = 4096;            // 4 grid-stride iterations per thread at D=16M
    const int maxBlocks = (n4 + threads - 1) / threads;
    if (blocks > maxBlocks) blocks = maxBlocks;

    dlrm_fused_kernel<<<blocks, threads>>>(
        (const float4*)x, (const float4*)l0, (const float4*)l1, (const float4*)l2,
        (float4*)out, out + D, n4);
}